// round 5
// baseline (speedup 1.0000x reference)
#include <cuda_runtime.h>
#include <cuda_fp16.h>
#include <math.h>
#include <stdint.h>

// Problem constants
#define Bn  2
#define Sn  2048
#define Dn  1024
#define Hn  16
#define HDn 64
#define Mn  (Bn * Sn)   // 4096

// Scratch (static device allocations — no cudaMalloc anywhere)
__device__ __half g_xh[(size_t)Mn * Dn];           // 8 MB
__device__ __half g_Wh[4][(size_t)Dn * Dn];        // 8 MB  Wq,Wk,Wv,Wo fp16
__device__ __half g_Qh[(size_t)Mn * Dn];           // 8 MB
__device__ __half g_Kh[(size_t)Mn * Dn];           // 8 MB
__device__ __half g_Vh[(size_t)Mn * Dn];           // 8 MB
__device__ __half g_Vt[(size_t)Bn * Dn * Sn];      // 8 MB  V transposed [b][d][tok]
__device__ __half g_P[(size_t)Bn * Hn * Sn * Sn];  // 256 MB fp16 probs
__device__ __half g_AOh[(size_t)Mn * Dn];          // 8 MB

// ---------------------------------------------------------------------------
// PTX helpers
// ---------------------------------------------------------------------------
__device__ __forceinline__ uint32_t smem_u32(const void* p) {
    return (uint32_t)__cvta_generic_to_shared(p);
}
__device__ __forceinline__ void cp16(uint32_t dst, const void* src) {
    asm volatile("cp.async.cg.shared.global [%0], [%1], 16;\n" :: "r"(dst), "l"(src));
}
__device__ __forceinline__ void cp_commit() { asm volatile("cp.async.commit_group;\n"); }
__device__ __forceinline__ void cp_wait0()  { asm volatile("cp.async.wait_group 0;\n"); }

__device__ __forceinline__ void ldsm4(uint32_t& r0, uint32_t& r1, uint32_t& r2, uint32_t& r3,
                                      uint32_t addr) {
    asm volatile("ldmatrix.sync.aligned.m8n8.x4.shared.b16 {%0,%1,%2,%3}, [%4];\n"
                 : "=r"(r0), "=r"(r1), "=r"(r2), "=r"(r3) : "r"(addr));
}
__device__ __forceinline__ void ldsm2(uint32_t& r0, uint32_t& r1, uint32_t addr) {
    asm volatile("ldmatrix.sync.aligned.m8n8.x2.shared.b16 {%0,%1}, [%2];\n"
                 : "=r"(r0), "=r"(r1) : "r"(addr));
}
__device__ __forceinline__ void mma16816(float* c,
                                         uint32_t a0, uint32_t a1, uint32_t a2, uint32_t a3,
                                         uint32_t b0, uint32_t b1) {
    asm volatile(
        "mma.sync.aligned.m16n8k16.row.col.f32.f16.f16.f32 "
        "{%0,%1,%2,%3},{%4,%5,%6,%7},{%8,%9},{%0,%1,%2,%3};\n"
        : "+f"(c[0]), "+f"(c[1]), "+f"(c[2]), "+f"(c[3])
        : "r"(a0), "r"(a1), "r"(a2), "r"(a3), "r"(b0), "r"(b1));
}

// 64B-row swizzle (row stride 64B = 4 chunks of 16B)
__device__ __forceinline__ uint32_t sw_off(int row, int chunk) {
    return ((uint32_t)row << 6) + ((uint32_t)((chunk ^ (row & 3) ^ ((row >> 2) & 1))) << 4);
}
// 128B-row swizzle (row stride 128B = 8 chunks of 16B): phys = c ^ (row&7)
__device__ __forceinline__ uint32_t sw128(int row, int chunk) {
    return ((uint32_t)row << 7) + ((uint32_t)((chunk ^ (row & 7))) << 4);
}

// ---------------------------------------------------------------------------
// fp16 NT GEMM core (unchanged, validated): C = scale*A*W^T (+bias)
// Block 128x128, BK=32, 256 thr, warp tile 32x64, cp.async double-buffered.
// ---------------------------------------------------------------------------
template <bool OUT_HALF>
__device__ __forceinline__ void gemm_nt_f16(
    const __half* __restrict__ A, int lda,
    const __half* __restrict__ W, int ldw,
    const float* __restrict__ bias,
    void* __restrict__ Cv, int ldc,
    int K, float scale, int bm, int bn)
{
    __shared__ __align__(16) char As[2][8192];
    __shared__ __align__(16) char Ws[2][8192];

    const int tid  = threadIdx.x;
    const int lane = tid & 31;
    const int warp = tid >> 5;
    const int grp  = lane >> 2;
    const int tig  = lane & 3;
    const int wm   = (warp & 3) * 32;
    const int wn   = (warp >> 2) * 64;
    const int lrow = tid >> 1;
    const int lc2  = (tid & 1) * 2;

    uint32_t asb[2] = { smem_u32(As[0]), smem_u32(As[1]) };
    uint32_t wsb[2] = { smem_u32(Ws[0]), smem_u32(Ws[1]) };

    const __half* Ag = A + (size_t)(bm + lrow) * lda;
    const __half* Wg = W + (size_t)(bn + lrow) * ldw;

    float acc[2][8][4] = {};

    const int nIter = K >> 5;
    cp16(asb[0] + sw_off(lrow, lc2),     Ag + lc2 * 8);
    cp16(asb[0] + sw_off(lrow, lc2 + 1), Ag + lc2 * 8 + 8);
    cp16(wsb[0] + sw_off(lrow, lc2),     Wg + lc2 * 8);
    cp16(wsb[0] + sw_off(lrow, lc2 + 1), Wg + lc2 * 8 + 8);
    cp_commit();

    for (int it = 0; it < nIter; ++it) {
        const int buf = it & 1;
        cp_wait0();
        __syncthreads();
        if (it + 1 < nIter) {
            const int k0 = (it + 1) << 5;
            cp16(asb[buf ^ 1] + sw_off(lrow, lc2),     Ag + k0 + lc2 * 8);
            cp16(asb[buf ^ 1] + sw_off(lrow, lc2 + 1), Ag + k0 + lc2 * 8 + 8);
            cp16(wsb[buf ^ 1] + sw_off(lrow, lc2),     Wg + k0 + lc2 * 8);
            cp16(wsb[buf ^ 1] + sw_off(lrow, lc2 + 1), Wg + k0 + lc2 * 8 + 8);
            cp_commit();
        }
        #pragma unroll
        for (int ks = 0; ks < 2; ++ks) {
            const int frow = (lane & 7) + ((lane >> 3) & 1) * 8;
            const int fch  = ks * 2 + (lane >> 4);
            uint32_t a[2][4];
            #pragma unroll
            for (int mi = 0; mi < 2; ++mi)
                ldsm4(a[mi][0], a[mi][1], a[mi][2], a[mi][3],
                      asb[buf] + sw_off(wm + mi * 16 + frow, fch));
            uint32_t b[8][2];
            #pragma unroll
            for (int nj = 0; nj < 4; ++nj) {
                uint32_t r0, r1, r2, r3;
                ldsm4(r0, r1, r2, r3, wsb[buf] + sw_off(wn + nj * 16 + frow, fch));
                b[nj * 2][0] = r0;  b[nj * 2][1] = r2;
                b[nj * 2 + 1][0] = r1;  b[nj * 2 + 1][1] = r3;
            }
            #pragma unroll
            for (int mi = 0; mi < 2; ++mi)
                #pragma unroll
                for (int ni = 0; ni < 8; ++ni)
                    mma16816(acc[mi][ni], a[mi][0], a[mi][1], a[mi][2], a[mi][3],
                             b[ni][0], b[ni][1]);
        }
    }

    #pragma unroll
    for (int mi = 0; mi < 2; ++mi) {
        const int r0 = bm + wm + mi * 16 + grp;
        #pragma unroll
        for (int ni = 0; ni < 8; ++ni) {
            const int c0 = bn + wn + ni * 8 + 2 * tig;
            float bx = 0.f, by = 0.f;
            if (bias) { bx = bias[c0]; by = bias[c0 + 1]; }
            const float x0 = acc[mi][ni][0] * scale + bx;
            const float y0 = acc[mi][ni][1] * scale + by;
            const float x1 = acc[mi][ni][2] * scale + bx;
            const float y1 = acc[mi][ni][3] * scale + by;
            if (OUT_HALF) {
                __half* C = (__half*)Cv;
                *(__half2*)&C[(size_t)r0 * ldc + c0]       = __floats2half2_rn(x0, y0);
                *(__half2*)&C[(size_t)(r0 + 8) * ldc + c0] = __floats2half2_rn(x1, y1);
            } else {
                float* C = (float*)Cv;
                *(float2*)&C[(size_t)r0 * ldc + c0]       = make_float2(x0, y0);
                *(float2*)&C[(size_t)(r0 + 8) * ldc + c0] = make_float2(x1, y1);
            }
        }
    }
}

// Fused QKV projection: blockIdx.z selects {Q,K,V}
__global__ void __launch_bounds__(256) qkv_h(
    const __half* __restrict__ xh,
    const float* __restrict__ bq, const float* __restrict__ bk,
    const float* __restrict__ bv)
{
    const int which = blockIdx.z;
    const __half* W = g_Wh[which];
    const float* bias = (which == 0) ? bq : (which == 1) ? bk : bv;
    __half* C = (which == 0) ? g_Qh : (which == 1) ? g_Kh : g_Vh;
    gemm_nt_f16<true>(xh, Dn, W, Dn, bias, C, Dn, Dn, 1.0f,
                      blockIdx.y * 128, blockIdx.x * 128);
}

// Final projection: out fp32
__global__ void __launch_bounds__(256) proj_f(
    const __half* __restrict__ A, const __half* __restrict__ W,
    const float* __restrict__ bias, float* __restrict__ C)
{
    gemm_nt_f16<false>(A, Dn, W, Dn, bias, C, Dn, Dn, 1.0f,
                       blockIdx.y * 128, blockIdx.x * 128);
}

// ---------------------------------------------------------------------------
// FUSED scores + head-softmax: block = (b, 32 q, 32 k), loops all 16 heads.
// Per warp: one 16x8 output fragment per head; fragment layout identical
// across heads -> softmax over h is per-thread register math.
// Writes fp16 P (staged via smem for coalesced stores). No fp32 scores tensor.
// grid (Sn/32, Sn/32, Bn), 256 threads.
// ---------------------------------------------------------------------------
__global__ void __launch_bounds__(256) fused_scores_softmax()
{
    __shared__ __align__(16) char Qs[2][4096];   // 32 x 64 halfs, SW128
    __shared__ __align__(16) char Ks[2][4096];
    __shared__ __align__(16) __half Pt[Hn][32][36];

    const int b  = blockIdx.z;
    const int q0 = blockIdx.y * 32;
    const int k0 = blockIdx.x * 32;
    const int tid  = threadIdx.x;
    const int lane = tid & 31;
    const int warp = tid >> 5;
    const int grp  = lane >> 2;
    const int tig  = lane & 3;
    const int mrow = (warp & 1) * 16;   // warp's q offset in tile
    const int ncol = (warp >> 1) * 8;   // warp's k offset in tile
    const int lrow = tid >> 3;          // 0..31 load row
    const int lch  = tid & 7;           // 0..7 load chunk

    const __half* Qg = g_Qh + ((size_t)b * Sn + q0 + lrow) * Dn + lch * 8;
    const __half* Kg = g_Kh + ((size_t)b * Sn + k0 + lrow) * Dn + lch * 8;
    uint32_t qsb[2] = { smem_u32(Qs[0]), smem_u32(Qs[1]) };
    uint32_t ksb[2] = { smem_u32(Ks[0]), smem_u32(Ks[1]) };
    const uint32_t loff = sw128(lrow, lch);

    float acc[Hn][4];
    #pragma unroll
    for (int h = 0; h < Hn; ++h)
        #pragma unroll
        for (int p = 0; p < 4; ++p) acc[h][p] = 0.f;

    // prologue: head 0
    cp16(qsb[0] + loff, Qg);
    cp16(ksb[0] + loff, Kg);
    cp_commit();

    const int afrow = mrow + (lane & 7) + ((lane >> 3) & 1) * 8;
    const int bfrow = ncol + (lane & 7);
    const int bfsel = (lane >> 3) & 1;

    for (int h = 0; h < Hn; ++h) {
        const int buf = h & 1;
        cp_wait0();
        __syncthreads();
        if (h + 1 < Hn) {
            cp16(qsb[buf ^ 1] + loff, Qg + (h + 1) * HDn);
            cp16(ksb[buf ^ 1] + loff, Kg + (h + 1) * HDn);
            cp_commit();
        }
        #pragma unroll
        for (int s = 0; s < 4; ++s) {
            uint32_t a0, a1, a2, a3, b0, b1;
            ldsm4(a0, a1, a2, a3, qsb[buf] + sw128(afrow, 2 * s + (lane >> 4)));
            ldsm2(b0, b1, ksb[buf] + sw128(bfrow, 2 * s + bfsel));
            mma16816(acc[h], a0, a1, a2, a3, b0, b1);
        }
        __syncthreads();   // all warps done with buf before next iter overwrites buf^1's sibling
    }

    // softmax over heads, per position (scale 1/8 applied pre-max)
    #pragma unroll
    for (int p = 0; p < 4; ++p) {
        float mx = -1e30f;
        #pragma unroll
        for (int h = 0; h < Hn; ++h) {
            acc[h][p] *= 0.125f;
            mx = fmaxf(mx, acc[h][p]);
        }
        float sum = 0.f;
        #pragma unroll
        for (int h = 0; h < Hn; ++h) {
            acc[h][p] = __expf(acc[h][p] - mx);
            sum += acc[h][p];
        }
        const float inv = 1.f / sum;
        #pragma unroll
        for (int h = 0; h < Hn; ++h) acc[h][p] *= inv;
    }

    // stage to smem (fragment scatter), then coalesced global write
    #pragma unroll
    for (int h = 0; h < Hn; ++h) {
        *(__half2*)&Pt[h][mrow + grp][ncol + 2 * tig]     = __floats2half2_rn(acc[h][0], acc[h][1]);
        *(__half2*)&Pt[h][mrow + grp + 8][ncol + 2 * tig] = __floats2half2_rn(acc[h][2], acc[h][3]);
    }
    __syncthreads();

    const int wrow = tid >> 3;          // 0..31
    const int wcol = (tid & 7) * 4;     // 0..28
    #pragma unroll
    for (int h = 0; h < Hn; ++h) {
        uint2 v = *(uint2*)&Pt[h][wrow][wcol];
        *(uint2*)(g_P + (((size_t)b * Hn + h) * Sn + q0 + wrow) * Sn + k0 + wcol) = v;
    }
}

// ---------------------------------------------------------------------------
// Transpose Vh[b*S + tok][d] -> Vt[b][d][tok] (fp16), 64x64 tiles
// ---------------------------------------------------------------------------
__global__ void __launch_bounds__(256) transpose_v()
{
    __shared__ __half ts[64][72];
    const int t0 = blockIdx.x * 64;
    const int d0 = blockIdx.y * 64;
    const int b  = blockIdx.z;
    const int tid = threadIdx.x;

    const __half* src = g_Vh + ((size_t)b * Sn + t0) * Dn + d0;
    const int r = tid >> 2, c2 = (tid & 3) * 2;
    *(uint4*)&ts[r][c2 * 8]     = *(const uint4*)(src + (size_t)r * Dn + c2 * 8);
    *(uint4*)&ts[r][c2 * 8 + 8] = *(const uint4*)(src + (size_t)r * Dn + c2 * 8 + 8);
    __syncthreads();

    const int dl = tid >> 2, seg = tid & 3;
    __half tmp[16];
    #pragma unroll
    for (int j = 0; j < 16; ++j) tmp[j] = ts[seg * 16 + j][dl];
    __half* dst = g_Vt + ((size_t)b * Dn + d0 + dl) * Sn + t0 + seg * 16;
    *(uint4*)dst       = *(uint4*)tmp;
    *(uint4*)(dst + 8) = *(uint4*)(tmp + 8);
}

// ---------------------------------------------------------------------------
// AV: per (b,h): O[q,d] = sum_k P_h[q,k] * Vt_h[d,k]  (NT, N=64)
// ---------------------------------------------------------------------------
__global__ void __launch_bounds__(256) av_h()
{
    __shared__ __align__(16) char Ps[2][8192];
    __shared__ __align__(16) char Vs[2][4096];

    const int zb = blockIdx.z;
    const int b  = zb >> 4;
    const int h  = zb & 15;
    const __half* P  = g_P + (size_t)zb * Sn * Sn;
    const __half* Vt = g_Vt + ((size_t)b * Dn + h * HDn) * Sn;
    __half* C = g_AOh + (size_t)b * Sn * Dn + h * HDn;

    const int tid  = threadIdx.x;
    const int lane = tid & 31;
    const int warp = tid >> 5;
    const int grp  = lane >> 2;
    const int tig  = lane & 3;
    const int bm   = blockIdx.x * 128;
    const int wm   = warp * 16;
    const int prow = tid >> 1, pc2 = (tid & 1) * 2;
    const int vrow = tid >> 2, vc  = tid & 3;

    uint32_t psb[2] = { smem_u32(Ps[0]), smem_u32(Ps[1]) };
    uint32_t vsb[2] = { smem_u32(Vs[0]), smem_u32(Vs[1]) };

    const __half* Pg = P  + (size_t)(bm + prow) * Sn;
    const __half* Vg = Vt + (size_t)vrow * Sn;

    float acc[8][4] = {};

    cp16(psb[0] + sw_off(prow, pc2),     Pg + pc2 * 8);
    cp16(psb[0] + sw_off(prow, pc2 + 1), Pg + pc2 * 8 + 8);
    cp16(vsb[0] + sw_off(vrow, vc),      Vg + vc * 8);
    cp_commit();

    const int nIter = Sn >> 5;
    for (int it = 0; it < nIter; ++it) {
        const int buf = it & 1;
        cp_wait0();
        __syncthreads();
        if (it + 1 < nIter) {
            const int k0 = (it + 1) << 5;
            cp16(psb[buf ^ 1] + sw_off(prow, pc2),     Pg + k0 + pc2 * 8);
            cp16(psb[buf ^ 1] + sw_off(prow, pc2 + 1), Pg + k0 + pc2 * 8 + 8);
            cp16(vsb[buf ^ 1] + sw_off(vrow, vc),      Vg + k0 + vc * 8);
            cp_commit();
        }
        #pragma unroll
        for (int ks = 0; ks < 2; ++ks) {
            const int frow = (lane & 7) + ((lane >> 3) & 1) * 8;
            const int fch  = ks * 2 + (lane >> 4);
            uint32_t a[4];
            ldsm4(a[0], a[1], a[2], a[3], psb[buf] + sw_off(wm + frow, fch));
            uint32_t bfr[8][2];
            #pragma unroll
            for (int nj = 0; nj < 4; ++nj) {
                uint32_t r0, r1, r2, r3;
                ldsm4(r0, r1, r2, r3, vsb[buf] + sw_off(nj * 16 + frow, fch));
                bfr[nj * 2][0] = r0;  bfr[nj * 2][1] = r2;
                bfr[nj * 2 + 1][0] = r1;  bfr[nj * 2 + 1][1] = r3;
            }
            #pragma unroll
            for (int ni = 0; ni < 8; ++ni)
                mma16816(acc[ni], a[0], a[1], a[2], a[3], bfr[ni][0], bfr[ni][1]);
        }
    }

    const int r0 = bm + wm + grp;
    #pragma unroll
    for (int ni = 0; ni < 8; ++ni) {
        const int c0 = ni * 8 + 2 * tig;
        *(__half2*)&C[(size_t)r0 * Dn + c0]       = __floats2half2_rn(acc[ni][0], acc[ni][1]);
        *(__half2*)&C[(size_t)(r0 + 8) * Dn + c0] = __floats2half2_rn(acc[ni][2], acc[ni][3]);
    }
}

// ---------------------------------------------------------------------------
__global__ void __launch_bounds__(256) f32_to_f16(
    const float* __restrict__ s, __half* __restrict__ d)
{
    const size_t i = ((size_t)blockIdx.x * 256 + threadIdx.x) * 8;
    float4 a = *(const float4*)(s + i);
    float4 b = *(const float4*)(s + i + 4);
    __half2 h0 = __floats2half2_rn(a.x, a.y), h1 = __floats2half2_rn(a.z, a.w);
    __half2 h2 = __floats2half2_rn(b.x, b.y), h3 = __floats2half2_rn(b.z, b.w);
    uint4 o;
    o.x = *(uint32_t*)&h0; o.y = *(uint32_t*)&h1;
    o.z = *(uint32_t*)&h2; o.w = *(uint32_t*)&h3;
    *(uint4*)(d + i) = o;
}

// ---------------------------------------------------------------------------
extern "C" void kernel_launch(void* const* d_in, const int* in_sizes, int n_in,
                              void* d_out, int out_size)
{
    const float* x  = (const float*)d_in[0];
    const float* Wq = (const float*)d_in[1];
    const float* bq = (const float*)d_in[2];
    const float* Wk = (const float*)d_in[3];
    const float* bk = (const float*)d_in[4];
    const float* Wv = (const float*)d_in[5];
    const float* bv = (const float*)d_in[6];
    const float* Wo = (const float*)d_in[7];
    const float* bo = (const float*)d_in[8];
    float* out = (float*)d_out;

    __half *xh, *Wh, *AOh;
    cudaGetSymbolAddress((void**)&xh,  g_xh);
    cudaGetSymbolAddress((void**)&Wh,  g_Wh);
    cudaGetSymbolAddress((void**)&AOh, g_AOh);

    const size_t WN = (size_t)Dn * Dn;

    f32_to_f16<<<(unsigned)((size_t)Mn * Dn / 8 / 256), 256>>>(x,  xh);
    f32_to_f16<<<(unsigned)(WN / 8 / 256), 256>>>(Wq, Wh + 0 * WN);
    f32_to_f16<<<(unsigned)(WN / 8 / 256), 256>>>(Wk, Wh + 1 * WN);
    f32_to_f16<<<(unsigned)(WN / 8 / 256), 256>>>(Wv, Wh + 2 * WN);
    f32_to_f16<<<(unsigned)(WN / 8 / 256), 256>>>(Wo, Wh + 3 * WN);

    // Fused QKV projections (one launch, z = which)
    dim3 gqkv(Dn / 128, Mn / 128, 3);
    qkv_h<<<gqkv, 256>>>(xh, bq, bk, bv);

    // V transpose
    dim3 gtr(Sn / 64, Dn / 64, Bn);
    transpose_v<<<gtr, 256>>>();

    // Fused scores + head-softmax -> fp16 P
    dim3 gfs(Sn / 32, Sn / 32, Bn);
    fused_scores_softmax<<<gfs, 256>>>();

    // attn @ V
    dim3 gav(Sn / 128, 1, Bn * Hn);
    av_h<<<gav, 256>>>();

    // Output projection
    dim3 gproj(Dn / 128, Mn / 128);
    proj_f<<<gproj, 256>>>(AOh, Wh + 3 * WN, bo, out);
}

// round 6
// speedup vs baseline: 1.0673x; 1.0673x over previous
#include <cuda_runtime.h>
#include <cuda_fp16.h>
#include <math.h>
#include <stdint.h>

// Problem constants
#define Bn  2
#define Sn  2048
#define Dn  1024
#define Hn  16
#define HDn 64
#define Mn  (Bn * Sn)   // 4096

// Scratch (static device allocations — no cudaMalloc anywhere)
__device__ __half g_xh[(size_t)Mn * Dn];           // 8 MB
__device__ __half g_Wh[4][(size_t)Dn * Dn];        // 8 MB  Wq,Wk,Wv,Wo fp16
__device__ __half g_Qh[(size_t)Mn * Dn];           // 8 MB
__device__ __half g_Kh[(size_t)Mn * Dn];           // 8 MB
__device__ __half g_Vh[(size_t)Mn * Dn];           // 8 MB
__device__ __half g_Vt[(size_t)Bn * Dn * Sn];      // 8 MB  V transposed [b][d][tok]
__device__ __half g_P[(size_t)Bn * Hn * Sn * Sn];  // 256 MB fp16 probs
__device__ __half g_AOh[(size_t)Mn * Dn];          // 8 MB

// ---------------------------------------------------------------------------
// PTX helpers
// ---------------------------------------------------------------------------
__device__ __forceinline__ uint32_t smem_u32(const void* p) {
    return (uint32_t)__cvta_generic_to_shared(p);
}
__device__ __forceinline__ void cp16(uint32_t dst, const void* src) {
    asm volatile("cp.async.cg.shared.global [%0], [%1], 16;\n" :: "r"(dst), "l"(src));
}
__device__ __forceinline__ void cp_commit() { asm volatile("cp.async.commit_group;\n"); }
__device__ __forceinline__ void cp_wait0()  { asm volatile("cp.async.wait_group 0;\n"); }

__device__ __forceinline__ void ldsm4(uint32_t& r0, uint32_t& r1, uint32_t& r2, uint32_t& r3,
                                      uint32_t addr) {
    asm volatile("ldmatrix.sync.aligned.m8n8.x4.shared.b16 {%0,%1,%2,%3}, [%4];\n"
                 : "=r"(r0), "=r"(r1), "=r"(r2), "=r"(r3) : "r"(addr));
}
__device__ __forceinline__ void ldsm2(uint32_t& r0, uint32_t& r1, uint32_t addr) {
    asm volatile("ldmatrix.sync.aligned.m8n8.x2.shared.b16 {%0,%1}, [%2];\n"
                 : "=r"(r0), "=r"(r1) : "r"(addr));
}
__device__ __forceinline__ void mma16816(float* c,
                                         uint32_t a0, uint32_t a1, uint32_t a2, uint32_t a3,
                                         uint32_t b0, uint32_t b1) {
    asm volatile(
        "mma.sync.aligned.m16n8k16.row.col.f32.f16.f16.f32 "
        "{%0,%1,%2,%3},{%4,%5,%6,%7},{%8,%9},{%0,%1,%2,%3};\n"
        : "+f"(c[0]), "+f"(c[1]), "+f"(c[2]), "+f"(c[3])
        : "r"(a0), "r"(a1), "r"(a2), "r"(a3), "r"(b0), "r"(b1));
}

// 64B-row swizzle (row stride 64B = 4 chunks of 16B)
__device__ __forceinline__ uint32_t sw_off(int row, int chunk) {
    return ((uint32_t)row << 6) + ((uint32_t)((chunk ^ (row & 3) ^ ((row >> 2) & 1))) << 4);
}
// 2048B-row swizzle (128 chunks of 16B per row): phys = c ^ (row & 7)
__device__ __forceinline__ uint32_t sw2048(int row, int chunk) {
    return ((uint32_t)row << 11) + ((uint32_t)((chunk ^ (row & 7))) << 4);
}

// ---------------------------------------------------------------------------
// fp16 NT GEMM core (validated): C = scale*A*W^T (+bias)
// Block 128x128, BK=32, 256 thr, warp tile 32x64, cp.async double-buffered.
// ---------------------------------------------------------------------------
template <bool OUT_HALF>
__device__ __forceinline__ void gemm_nt_f16(
    const __half* __restrict__ A, int lda,
    const __half* __restrict__ W, int ldw,
    const float* __restrict__ bias,
    void* __restrict__ Cv, int ldc,
    int K, float scale, int bm, int bn)
{
    __shared__ __align__(16) char As[2][8192];
    __shared__ __align__(16) char Ws[2][8192];

    const int tid  = threadIdx.x;
    const int lane = tid & 31;
    const int warp = tid >> 5;
    const int grp  = lane >> 2;
    const int tig  = lane & 3;
    const int wm   = (warp & 3) * 32;
    const int wn   = (warp >> 2) * 64;
    const int lrow = tid >> 1;
    const int lc2  = (tid & 1) * 2;

    uint32_t asb[2] = { smem_u32(As[0]), smem_u32(As[1]) };
    uint32_t wsb[2] = { smem_u32(Ws[0]), smem_u32(Ws[1]) };

    const __half* Ag = A + (size_t)(bm + lrow) * lda;
    const __half* Wg = W + (size_t)(bn + lrow) * ldw;

    float acc[2][8][4] = {};

    const int nIter = K >> 5;
    cp16(asb[0] + sw_off(lrow, lc2),     Ag + lc2 * 8);
    cp16(asb[0] + sw_off(lrow, lc2 + 1), Ag + lc2 * 8 + 8);
    cp16(wsb[0] + sw_off(lrow, lc2),     Wg + lc2 * 8);
    cp16(wsb[0] + sw_off(lrow, lc2 + 1), Wg + lc2 * 8 + 8);
    cp_commit();

    for (int it = 0; it < nIter; ++it) {
        const int buf = it & 1;
        cp_wait0();
        __syncthreads();
        if (it + 1 < nIter) {
            const int k0 = (it + 1) << 5;
            cp16(asb[buf ^ 1] + sw_off(lrow, lc2),     Ag + k0 + lc2 * 8);
            cp16(asb[buf ^ 1] + sw_off(lrow, lc2 + 1), Ag + k0 + lc2 * 8 + 8);
            cp16(wsb[buf ^ 1] + sw_off(lrow, lc2),     Wg + k0 + lc2 * 8);
            cp16(wsb[buf ^ 1] + sw_off(lrow, lc2 + 1), Wg + k0 + lc2 * 8 + 8);
            cp_commit();
        }
        #pragma unroll
        for (int ks = 0; ks < 2; ++ks) {
            const int frow = (lane & 7) + ((lane >> 3) & 1) * 8;
            const int fch  = ks * 2 + (lane >> 4);
            uint32_t a[2][4];
            #pragma unroll
            for (int mi = 0; mi < 2; ++mi)
                ldsm4(a[mi][0], a[mi][1], a[mi][2], a[mi][3],
                      asb[buf] + sw_off(wm + mi * 16 + frow, fch));
            uint32_t b[8][2];
            #pragma unroll
            for (int nj = 0; nj < 4; ++nj) {
                uint32_t r0, r1, r2, r3;
                ldsm4(r0, r1, r2, r3, wsb[buf] + sw_off(wn + nj * 16 + frow, fch));
                b[nj * 2][0] = r0;  b[nj * 2][1] = r2;
                b[nj * 2 + 1][0] = r1;  b[nj * 2 + 1][1] = r3;
            }
            #pragma unroll
            for (int mi = 0; mi < 2; ++mi)
                #pragma unroll
                for (int ni = 0; ni < 8; ++ni)
                    mma16816(acc[mi][ni], a[mi][0], a[mi][1], a[mi][2], a[mi][3],
                             b[ni][0], b[ni][1]);
        }
    }

    #pragma unroll
    for (int mi = 0; mi < 2; ++mi) {
        const int r0 = bm + wm + mi * 16 + grp;
        #pragma unroll
        for (int ni = 0; ni < 8; ++ni) {
            const int c0 = bn + wn + ni * 8 + 2 * tig;
            float bx = 0.f, by = 0.f;
            if (bias) { bx = bias[c0]; by = bias[c0 + 1]; }
            const float x0 = acc[mi][ni][0] * scale + bx;
            const float y0 = acc[mi][ni][1] * scale + by;
            const float x1 = acc[mi][ni][2] * scale + bx;
            const float y1 = acc[mi][ni][3] * scale + by;
            if (OUT_HALF) {
                __half* C = (__half*)Cv;
                *(__half2*)&C[(size_t)r0 * ldc + c0]       = __floats2half2_rn(x0, y0);
                *(__half2*)&C[(size_t)(r0 + 8) * ldc + c0] = __floats2half2_rn(x1, y1);
            } else {
                float* C = (float*)Cv;
                *(float2*)&C[(size_t)r0 * ldc + c0]       = make_float2(x0, y0);
                *(float2*)&C[(size_t)(r0 + 8) * ldc + c0] = make_float2(x1, y1);
            }
        }
    }
}

// Fused QKV projection: blockIdx.z selects {Q,K,V}
__global__ void __launch_bounds__(256) qkv_h(
    const __half* __restrict__ xh,
    const float* __restrict__ bq, const float* __restrict__ bk,
    const float* __restrict__ bv)
{
    const int which = blockIdx.z;
    const __half* W = g_Wh[which];
    const float* bias = (which == 0) ? bq : (which == 1) ? bk : bv;
    __half* C = (which == 0) ? g_Qh : (which == 1) ? g_Kh : g_Vh;
    gemm_nt_f16<true>(xh, Dn, W, Dn, bias, C, Dn, Dn, 1.0f,
                      blockIdx.y * 128, blockIdx.x * 128);
}

// Final projection: out fp32
__global__ void __launch_bounds__(256) proj_f(
    const __half* __restrict__ A, const __half* __restrict__ W,
    const float* __restrict__ bias, float* __restrict__ C)
{
    gemm_nt_f16<false>(A, Dn, W, Dn, bias, C, Dn, Dn, 1.0f,
                       blockIdx.y * 128, blockIdx.x * 128);
}

// ---------------------------------------------------------------------------
// FUSED scores + head-softmax, v2: whole 16-head Q/K tiles resident in smem.
// Block = (b, 32 q, 32 k). 128 KB dynamic smem (64 KB Q + 64 KB K, SW2048).
// One load burst -> one barrier -> 64 unrolled ldsm/mma per warp (no syncs)
// -> register softmax over h -> stage to smem (aliased) -> coalesced P write.
// grid (Sn/32, Sn/32, Bn), 256 threads.
// ---------------------------------------------------------------------------
#define FS_SMEM 131072

__global__ void __launch_bounds__(256) fused_scores_softmax_v2()
{
    extern __shared__ __align__(16) char smem[];
    uint32_t qsb = smem_u32(smem);
    uint32_t ksb = qsb + 65536;

    const int b  = blockIdx.z;
    const int q0 = blockIdx.y * 32;
    const int k0 = blockIdx.x * 32;
    const int tid  = threadIdx.x;
    const int lane = tid & 31;
    const int warp = tid >> 5;
    const int grp  = lane >> 2;
    const int tig  = lane & 3;
    const int mrow = (warp & 1) * 16;   // warp's q offset in tile
    const int ncol = (warp >> 1) * 8;   // warp's k offset in tile
    const int lrow = tid >> 3;          // 0..31 load row
    const int lc0  = tid & 7;           // base chunk

    const __half* Qg = g_Qh + ((size_t)b * Sn + q0 + lrow) * Dn;
    const __half* Kg = g_Kh + ((size_t)b * Sn + k0 + lrow) * Dn;

    // one-shot load: all 16 heads of both tiles (16 chunks/thread each)
    #pragma unroll
    for (int i = 0; i < 16; ++i) {
        const int c = lc0 + 8 * i;
        cp16(qsb + sw2048(lrow, c), Qg + c * 8);
        cp16(ksb + sw2048(lrow, c), Kg + c * 8);
    }
    cp_commit();
    cp_wait0();
    __syncthreads();

    float acc[Hn][4];
    #pragma unroll
    for (int h = 0; h < Hn; ++h)
        #pragma unroll
        for (int p = 0; p < 4; ++p) acc[h][p] = 0.f;

    const int afrow = mrow + (lane & 7) + ((lane >> 3) & 1) * 8;
    const int asel  = lane >> 4;
    const int bfrow = ncol + (lane & 7);
    const int bsel  = (lane >> 3) & 1;

    // barrier-free MMA stream: 16 heads x 4 ksteps
    #pragma unroll
    for (int h = 0; h < Hn; ++h) {
        #pragma unroll
        for (int s = 0; s < 4; ++s) {
            uint32_t a0, a1, a2, a3, b0, b1;
            ldsm4(a0, a1, a2, a3, qsb + sw2048(afrow, 8 * h + 2 * s + asel));
            ldsm2(b0, b1,         ksb + sw2048(bfrow, 8 * h + 2 * s + bsel));
            mma16816(acc[h], a0, a1, a2, a3, b0, b1);
        }
    }

    // softmax over heads, per position (scale 1/8 applied pre-max)
    #pragma unroll
    for (int p = 0; p < 4; ++p) {
        float mx = -1e30f;
        #pragma unroll
        for (int h = 0; h < Hn; ++h) {
            acc[h][p] *= 0.125f;
            mx = fmaxf(mx, acc[h][p]);
        }
        float sum = 0.f;
        #pragma unroll
        for (int h = 0; h < Hn; ++h) {
            acc[h][p] = __expf(acc[h][p] - mx);
            sum += acc[h][p];
        }
        const float inv = 1.f / sum;
        #pragma unroll
        for (int h = 0; h < Hn; ++h) acc[h][p] *= inv;
    }

    __syncthreads();   // Q/K smem dead; alias as Pt staging
    __half (*Pt)[32][36] = reinterpret_cast<__half (*)[32][36]>(smem);

    #pragma unroll
    for (int h = 0; h < Hn; ++h) {
        *(__half2*)&Pt[h][mrow + grp][ncol + 2 * tig]     = __floats2half2_rn(acc[h][0], acc[h][1]);
        *(__half2*)&Pt[h][mrow + grp + 8][ncol + 2 * tig] = __floats2half2_rn(acc[h][2], acc[h][3]);
    }
    __syncthreads();

    const int wrow = tid >> 3;          // 0..31
    const int wcol = (tid & 7) * 4;     // 0..28
    #pragma unroll
    for (int h = 0; h < Hn; ++h) {
        uint2 v = *(uint2*)&Pt[h][wrow][wcol];
        *(uint2*)(g_P + (((size_t)b * Hn + h) * Sn + q0 + wrow) * Sn + k0 + wcol) = v;
    }
}

// ---------------------------------------------------------------------------
// Transpose Vh[b*S + tok][d] -> Vt[b][d][tok] (fp16), 64x64 tiles
// ---------------------------------------------------------------------------
__global__ void __launch_bounds__(256) transpose_v()
{
    __shared__ __half ts[64][72];
    const int t0 = blockIdx.x * 64;
    const int d0 = blockIdx.y * 64;
    const int b  = blockIdx.z;
    const int tid = threadIdx.x;

    const __half* src = g_Vh + ((size_t)b * Sn + t0) * Dn + d0;
    const int r = tid >> 2, c2 = (tid & 3) * 2;
    *(uint4*)&ts[r][c2 * 8]     = *(const uint4*)(src + (size_t)r * Dn + c2 * 8);
    *(uint4*)&ts[r][c2 * 8 + 8] = *(const uint4*)(src + (size_t)r * Dn + c2 * 8 + 8);
    __syncthreads();

    const int dl = tid >> 2, seg = tid & 3;
    __half tmp[16];
    #pragma unroll
    for (int j = 0; j < 16; ++j) tmp[j] = ts[seg * 16 + j][dl];
    __half* dst = g_Vt + ((size_t)b * Dn + d0 + dl) * Sn + t0 + seg * 16;
    *(uint4*)dst       = *(uint4*)tmp;
    *(uint4*)(dst + 8) = *(uint4*)(tmp + 8);
}

// ---------------------------------------------------------------------------
// AV: per (b,h): O[q,d] = sum_k P_h[q,k] * Vt_h[d,k]  (NT, N=64)
// ---------------------------------------------------------------------------
__global__ void __launch_bounds__(256) av_h()
{
    __shared__ __align__(16) char Ps[2][8192];
    __shared__ __align__(16) char Vs[2][4096];

    const int zb = blockIdx.z;
    const int b  = zb >> 4;
    const int h  = zb & 15;
    const __half* P  = g_P + (size_t)zb * Sn * Sn;
    const __half* Vt = g_Vt + ((size_t)b * Dn + h * HDn) * Sn;
    __half* C = g_AOh + (size_t)b * Sn * Dn + h * HDn;

    const int tid  = threadIdx.x;
    const int lane = tid & 31;
    const int warp = tid >> 5;
    const int grp  = lane >> 2;
    const int tig  = lane & 3;
    const int bm   = blockIdx.x * 128;
    const int wm   = warp * 16;
    const int prow = tid >> 1, pc2 = (tid & 1) * 2;
    const int vrow = tid >> 2, vc  = tid & 3;

    uint32_t psb[2] = { smem_u32(Ps[0]), smem_u32(Ps[1]) };
    uint32_t vsb[2] = { smem_u32(Vs[0]), smem_u32(Vs[1]) };

    const __half* Pg = P  + (size_t)(bm + prow) * Sn;
    const __half* Vg = Vt + (size_t)vrow * Sn;

    float acc[8][4] = {};

    cp16(psb[0] + sw_off(prow, pc2),     Pg + pc2 * 8);
    cp16(psb[0] + sw_off(prow, pc2 + 1), Pg + pc2 * 8 + 8);
    cp16(vsb[0] + sw_off(vrow, vc),      Vg + vc * 8);
    cp_commit();

    const int nIter = Sn >> 5;
    for (int it = 0; it < nIter; ++it) {
        const int buf = it & 1;
        cp_wait0();
        __syncthreads();
        if (it + 1 < nIter) {
            const int k0 = (it + 1) << 5;
            cp16(psb[buf ^ 1] + sw_off(prow, pc2),     Pg + k0 + pc2 * 8);
            cp16(psb[buf ^ 1] + sw_off(prow, pc2 + 1), Pg + k0 + pc2 * 8 + 8);
            cp16(vsb[buf ^ 1] + sw_off(vrow, vc),      Vg + k0 + vc * 8);
            cp_commit();
        }
        #pragma unroll
        for (int ks = 0; ks < 2; ++ks) {
            const int frow = (lane & 7) + ((lane >> 3) & 1) * 8;
            const int fch  = ks * 2 + (lane >> 4);
            uint32_t a[4];
            ldsm4(a[0], a[1], a[2], a[3], psb[buf] + sw_off(wm + frow, fch));
            uint32_t bfr[8][2];
            #pragma unroll
            for (int nj = 0; nj < 4; ++nj) {
                uint32_t r0, r1, r2, r3;
                ldsm4(r0, r1, r2, r3, vsb[buf] + sw_off(nj * 16 + frow, fch));
                bfr[nj * 2][0] = r0;  bfr[nj * 2][1] = r2;
                bfr[nj * 2 + 1][0] = r1;  bfr[nj * 2 + 1][1] = r3;
            }
            #pragma unroll
            for (int ni = 0; ni < 8; ++ni)
                mma16816(acc[ni], a[0], a[1], a[2], a[3], bfr[ni][0], bfr[ni][1]);
        }
    }

    const int r0 = bm + wm + grp;
    #pragma unroll
    for (int ni = 0; ni < 8; ++ni) {
        const int c0 = ni * 8 + 2 * tig;
        *(__half2*)&C[(size_t)r0 * Dn + c0]       = __floats2half2_rn(acc[ni][0], acc[ni][1]);
        *(__half2*)&C[(size_t)(r0 + 8) * Dn + c0] = __floats2half2_rn(acc[ni][2], acc[ni][3]);
    }
}

// ---------------------------------------------------------------------------
__global__ void __launch_bounds__(256) f32_to_f16(
    const float* __restrict__ s, __half* __restrict__ d)
{
    const size_t i = ((size_t)blockIdx.x * 256 + threadIdx.x) * 8;
    float4 a = *(const float4*)(s + i);
    float4 b = *(const float4*)(s + i + 4);
    __half2 h0 = __floats2half2_rn(a.x, a.y), h1 = __floats2half2_rn(a.z, a.w);
    __half2 h2 = __floats2half2_rn(b.x, b.y), h3 = __floats2half2_rn(b.z, b.w);
    uint4 o;
    o.x = *(uint32_t*)&h0; o.y = *(uint32_t*)&h1;
    o.z = *(uint32_t*)&h2; o.w = *(uint32_t*)&h3;
    *(uint4*)(d + i) = o;
}

// ---------------------------------------------------------------------------
extern "C" void kernel_launch(void* const* d_in, const int* in_sizes, int n_in,
                              void* d_out, int out_size)
{
    const float* x  = (const float*)d_in[0];
    const float* Wq = (const float*)d_in[1];
    const float* bq = (const float*)d_in[2];
    const float* Wk = (const float*)d_in[3];
    const float* bk = (const float*)d_in[4];
    const float* Wv = (const float*)d_in[5];
    const float* bv = (const float*)d_in[6];
    const float* Wo = (const float*)d_in[7];
    const float* bo = (const float*)d_in[8];
    float* out = (float*)d_out;

    __half *xh, *Wh, *AOh;
    cudaGetSymbolAddress((void**)&xh,  g_xh);
    cudaGetSymbolAddress((void**)&Wh,  g_Wh);
    cudaGetSymbolAddress((void**)&AOh, g_AOh);

    const size_t WN = (size_t)Dn * Dn;

    f32_to_f16<<<(unsigned)((size_t)Mn * Dn / 8 / 256), 256>>>(x,  xh);
    f32_to_f16<<<(unsigned)(WN / 8 / 256), 256>>>(Wq, Wh + 0 * WN);
    f32_to_f16<<<(unsigned)(WN / 8 / 256), 256>>>(Wk, Wh + 1 * WN);
    f32_to_f16<<<(unsigned)(WN / 8 / 256), 256>>>(Wv, Wh + 2 * WN);
    f32_to_f16<<<(unsigned)(WN / 8 / 256), 256>>>(Wo, Wh + 3 * WN);

    // Fused QKV projections (one launch, z = which)
    dim3 gqkv(Dn / 128, Mn / 128, 3);
    qkv_h<<<gqkv, 256>>>(xh, bq, bk, bv);

    // V transpose
    dim3 gtr(Sn / 64, Dn / 64, Bn);
    transpose_v<<<gtr, 256>>>();

    // Fused scores + head-softmax -> fp16 P (v2: resident tiles, no inner syncs)
    cudaFuncSetAttribute(fused_scores_softmax_v2,
                         cudaFuncAttributeMaxDynamicSharedMemorySize, FS_SMEM);
    dim3 gfs(Sn / 32, Sn / 32, Bn);
    fused_scores_softmax_v2<<<gfs, 256, FS_SMEM>>>();

    // attn @ V
    dim3 gav(Sn / 128, 1, Bn * Hn);
    av_h<<<gav, 256>>>();

    // Output projection
    dim3 gproj(Dn / 128, Mn / 128);
    proj_f<<<gproj, 256>>>(AOh, Wh + 3 * WN, bo, out);
}

// round 7
// speedup vs baseline: 1.2270x; 1.1496x over previous
#include <cuda_runtime.h>
#include <cuda_fp16.h>
#include <math.h>
#include <stdint.h>

// Problem constants
#define Bn  2
#define Sn  2048
#define Dn  1024
#define Hn  16
#define HDn 64
#define Mn  (Bn * Sn)   // 4096

// Scratch (static device allocations — no cudaMalloc anywhere)
__device__ __half g_xh[(size_t)Mn * Dn];           // 8 MB
__device__ __half g_Wh[4][(size_t)Dn * Dn];        // 8 MB  Wq,Wk,Wv,Wo fp16
__device__ __half g_Qh[(size_t)Mn * Dn];           // 8 MB
__device__ __half g_Kh[(size_t)Mn * Dn];           // 8 MB
__device__ __half g_Vh[(size_t)Mn * Dn];           // 8 MB
__device__ __half g_Vt[(size_t)Bn * Dn * Sn];      // 8 MB  V transposed [b][d][tok]
__device__ __half g_SP[(size_t)Bn * Hn * Sn * Sn]; // 256 MB fp16 scores -> probs (in place)
__device__ __half g_AOh[(size_t)Mn * Dn];          // 8 MB

// ---------------------------------------------------------------------------
// PTX helpers
// ---------------------------------------------------------------------------
__device__ __forceinline__ uint32_t smem_u32(const void* p) {
    return (uint32_t)__cvta_generic_to_shared(p);
}
__device__ __forceinline__ void cp16(uint32_t dst, const void* src) {
    asm volatile("cp.async.cg.shared.global [%0], [%1], 16;\n" :: "r"(dst), "l"(src));
}
__device__ __forceinline__ void cp_commit() { asm volatile("cp.async.commit_group;\n"); }
__device__ __forceinline__ void cp_wait0()  { asm volatile("cp.async.wait_group 0;\n"); }

__device__ __forceinline__ void ldsm4(uint32_t& r0, uint32_t& r1, uint32_t& r2, uint32_t& r3,
                                      uint32_t addr) {
    asm volatile("ldmatrix.sync.aligned.m8n8.x4.shared.b16 {%0,%1,%2,%3}, [%4];\n"
                 : "=r"(r0), "=r"(r1), "=r"(r2), "=r"(r3) : "r"(addr));
}
__device__ __forceinline__ void mma16816(float* c,
                                         uint32_t a0, uint32_t a1, uint32_t a2, uint32_t a3,
                                         uint32_t b0, uint32_t b1) {
    asm volatile(
        "mma.sync.aligned.m16n8k16.row.col.f32.f16.f16.f32 "
        "{%0,%1,%2,%3},{%4,%5,%6,%7},{%8,%9},{%0,%1,%2,%3};\n"
        : "+f"(c[0]), "+f"(c[1]), "+f"(c[2]), "+f"(c[3])
        : "r"(a0), "r"(a1), "r"(a2), "r"(a3), "r"(b0), "r"(b1));
}

// 64B-row swizzle (row stride 64B = 4 chunks of 16B)
__device__ __forceinline__ uint32_t sw_off(int row, int chunk) {
    return ((uint32_t)row << 6) + ((uint32_t)((chunk ^ (row & 3) ^ ((row >> 2) & 1))) << 4);
}

// ---------------------------------------------------------------------------
// fp16 NT GEMM core (validated): C = scale*A*W^T (+bias)
// Block 128x128, BK=32, 256 thr, warp tile 32x64, cp.async double-buffered.
// ---------------------------------------------------------------------------
template <bool OUT_HALF>
__device__ __forceinline__ void gemm_nt_f16(
    const __half* __restrict__ A, int lda,
    const __half* __restrict__ W, int ldw,
    const float* __restrict__ bias,
    void* __restrict__ Cv, int ldc,
    int K, float scale, int bm, int bn)
{
    __shared__ __align__(16) char As[2][8192];
    __shared__ __align__(16) char Ws[2][8192];

    const int tid  = threadIdx.x;
    const int lane = tid & 31;
    const int warp = tid >> 5;
    const int grp  = lane >> 2;
    const int tig  = lane & 3;
    const int wm   = (warp & 3) * 32;
    const int wn   = (warp >> 2) * 64;
    const int lrow = tid >> 1;
    const int lc2  = (tid & 1) * 2;

    uint32_t asb[2] = { smem_u32(As[0]), smem_u32(As[1]) };
    uint32_t wsb[2] = { smem_u32(Ws[0]), smem_u32(Ws[1]) };

    const __half* Ag = A + (size_t)(bm + lrow) * lda;
    const __half* Wg = W + (size_t)(bn + lrow) * ldw;

    float acc[2][8][4] = {};

    const int nIter = K >> 5;
    cp16(asb[0] + sw_off(lrow, lc2),     Ag + lc2 * 8);
    cp16(asb[0] + sw_off(lrow, lc2 + 1), Ag + lc2 * 8 + 8);
    cp16(wsb[0] + sw_off(lrow, lc2),     Wg + lc2 * 8);
    cp16(wsb[0] + sw_off(lrow, lc2 + 1), Wg + lc2 * 8 + 8);
    cp_commit();

    for (int it = 0; it < nIter; ++it) {
        const int buf = it & 1;
        cp_wait0();
        __syncthreads();
        if (it + 1 < nIter) {
            const int k0 = (it + 1) << 5;
            cp16(asb[buf ^ 1] + sw_off(lrow, lc2),     Ag + k0 + lc2 * 8);
            cp16(asb[buf ^ 1] + sw_off(lrow, lc2 + 1), Ag + k0 + lc2 * 8 + 8);
            cp16(wsb[buf ^ 1] + sw_off(lrow, lc2),     Wg + k0 + lc2 * 8);
            cp16(wsb[buf ^ 1] + sw_off(lrow, lc2 + 1), Wg + k0 + lc2 * 8 + 8);
            cp_commit();
        }
        #pragma unroll
        for (int ks = 0; ks < 2; ++ks) {
            const int frow = (lane & 7) + ((lane >> 3) & 1) * 8;
            const int fch  = ks * 2 + (lane >> 4);
            uint32_t a[2][4];
            #pragma unroll
            for (int mi = 0; mi < 2; ++mi)
                ldsm4(a[mi][0], a[mi][1], a[mi][2], a[mi][3],
                      asb[buf] + sw_off(wm + mi * 16 + frow, fch));
            uint32_t b[8][2];
            #pragma unroll
            for (int nj = 0; nj < 4; ++nj) {
                uint32_t r0, r1, r2, r3;
                ldsm4(r0, r1, r2, r3, wsb[buf] + sw_off(wn + nj * 16 + frow, fch));
                b[nj * 2][0] = r0;  b[nj * 2][1] = r2;
                b[nj * 2 + 1][0] = r1;  b[nj * 2 + 1][1] = r3;
            }
            #pragma unroll
            for (int mi = 0; mi < 2; ++mi)
                #pragma unroll
                for (int ni = 0; ni < 8; ++ni)
                    mma16816(acc[mi][ni], a[mi][0], a[mi][1], a[mi][2], a[mi][3],
                             b[ni][0], b[ni][1]);
        }
    }

    #pragma unroll
    for (int mi = 0; mi < 2; ++mi) {
        const int r0 = bm + wm + mi * 16 + grp;
        #pragma unroll
        for (int ni = 0; ni < 8; ++ni) {
            const int c0 = bn + wn + ni * 8 + 2 * tig;
            float bx = 0.f, by = 0.f;
            if (bias) { bx = bias[c0]; by = bias[c0 + 1]; }
            const float x0 = acc[mi][ni][0] * scale + bx;
            const float y0 = acc[mi][ni][1] * scale + by;
            const float x1 = acc[mi][ni][2] * scale + bx;
            const float y1 = acc[mi][ni][3] * scale + by;
            if (OUT_HALF) {
                __half* C = (__half*)Cv;
                *(__half2*)&C[(size_t)r0 * ldc + c0]       = __floats2half2_rn(x0, y0);
                *(__half2*)&C[(size_t)(r0 + 8) * ldc + c0] = __floats2half2_rn(x1, y1);
            } else {
                float* C = (float*)Cv;
                *(float2*)&C[(size_t)r0 * ldc + c0]       = make_float2(x0, y0);
                *(float2*)&C[(size_t)(r0 + 8) * ldc + c0] = make_float2(x1, y1);
            }
        }
    }
}

// Fused QKV projection: blockIdx.z selects {Q,K,V}
__global__ void __launch_bounds__(256) qkv_h(
    const __half* __restrict__ xh,
    const float* __restrict__ bq, const float* __restrict__ bk,
    const float* __restrict__ bv)
{
    const int which = blockIdx.z;
    const __half* W = g_Wh[which];
    const float* bias = (which == 0) ? bq : (which == 1) ? bk : bv;
    __half* C = (which == 0) ? g_Qh : (which == 1) ? g_Kh : g_Vh;
    gemm_nt_f16<true>(xh, Dn, W, Dn, bias, C, Dn, Dn, 1.0f,
                      blockIdx.y * 128, blockIdx.x * 128);
}

// Final projection: out fp32
__global__ void __launch_bounds__(256) proj_f(
    const __half* __restrict__ A, const __half* __restrict__ W,
    const float* __restrict__ bias, float* __restrict__ C)
{
    gemm_nt_f16<false>(A, Dn, W, Dn, bias, C, Dn, Dn, 1.0f,
                       blockIdx.y * 128, blockIdx.x * 128);
}

// Scores: per (b,h): S[q,k] = 0.125 * dot(Q_h[q,:], K_h[k,:]); fp16 out
__global__ void __launch_bounds__(256) scores_h()
{
    const int zb = blockIdx.z;
    const int b  = zb >> 4;
    const int h  = zb & 15;
    const __half* A = g_Qh + (size_t)b * Sn * Dn + h * HDn;
    const __half* W = g_Kh + (size_t)b * Sn * Dn + h * HDn;
    __half* C = g_SP + (size_t)zb * Sn * Sn;
    gemm_nt_f16<true>(A, Dn, W, Dn, nullptr, C, Sn, HDn, 0.125f,
                      blockIdx.y * 128, blockIdx.x * 128);
}

// ---------------------------------------------------------------------------
// Softmax over HEAD axis (axis=1, faithful), IN PLACE on fp16 buffer.
// Each thread handles 2 adjacent k positions (__half2 loads/stores).
// ---------------------------------------------------------------------------
__global__ void __launch_bounds__(256) softmax_h16()
{
    const size_t SS = (size_t)Sn * Sn;
    const size_t idx = (size_t)blockIdx.x * 256 + threadIdx.x;   // < Bn*SS/2
    const size_t b    = idx / (SS / 2);
    const size_t rem2 = idx % (SS / 2);
    __half* base = g_SP + b * Hn * SS + rem2 * 2;

    float vx[Hn], vy[Hn];
    float mx = -1e30f, my = -1e30f;
    #pragma unroll
    for (int h = 0; h < Hn; ++h) {
        float2 v = __half22float2(*(__half2*)&base[(size_t)h * SS]);
        vx[h] = v.x; vy[h] = v.y;
        mx = fmaxf(mx, v.x);
        my = fmaxf(my, v.y);
    }
    float sx = 0.f, sy = 0.f;
    #pragma unroll
    for (int h = 0; h < Hn; ++h) {
        vx[h] = __expf(vx[h] - mx);
        vy[h] = __expf(vy[h] - my);
        sx += vx[h]; sy += vy[h];
    }
    const float ix = 1.f / sx, iy = 1.f / sy;
    #pragma unroll
    for (int h = 0; h < Hn; ++h)
        *(__half2*)&base[(size_t)h * SS] = __floats2half2_rn(vx[h] * ix, vy[h] * iy);
}

// ---------------------------------------------------------------------------
// Transpose Vh[b*S + tok][d] -> Vt[b][d][tok] (fp16), 64x64 tiles
// ---------------------------------------------------------------------------
__global__ void __launch_bounds__(256) transpose_v()
{
    __shared__ __half ts[64][72];
    const int t0 = blockIdx.x * 64;
    const int d0 = blockIdx.y * 64;
    const int b  = blockIdx.z;
    const int tid = threadIdx.x;

    const __half* src = g_Vh + ((size_t)b * Sn + t0) * Dn + d0;
    const int r = tid >> 2, c2 = (tid & 3) * 2;
    *(uint4*)&ts[r][c2 * 8]     = *(const uint4*)(src + (size_t)r * Dn + c2 * 8);
    *(uint4*)&ts[r][c2 * 8 + 8] = *(const uint4*)(src + (size_t)r * Dn + c2 * 8 + 8);
    __syncthreads();

    const int dl = tid >> 2, seg = tid & 3;
    __half tmp[16];
    #pragma unroll
    for (int j = 0; j < 16; ++j) tmp[j] = ts[seg * 16 + j][dl];
    __half* dst = g_Vt + ((size_t)b * Dn + d0 + dl) * Sn + t0 + seg * 16;
    *(uint4*)dst       = *(uint4*)tmp;
    *(uint4*)(dst + 8) = *(uint4*)(tmp + 8);
}

// ---------------------------------------------------------------------------
// AV: per (b,h): O[q,d] = sum_k P_h[q,k] * Vt_h[d,k]  (NT, N=64)
// ---------------------------------------------------------------------------
__global__ void __launch_bounds__(256) av_h()
{
    __shared__ __align__(16) char Ps[2][8192];
    __shared__ __align__(16) char Vs[2][4096];

    const int zb = blockIdx.z;
    const int b  = zb >> 4;
    const int h  = zb & 15;
    const __half* P  = g_SP + (size_t)zb * Sn * Sn;
    const __half* Vt = g_Vt + ((size_t)b * Dn + h * HDn) * Sn;
    __half* C = g_AOh + (size_t)b * Sn * Dn + h * HDn;

    const int tid  = threadIdx.x;
    const int lane = tid & 31;
    const int warp = tid >> 5;
    const int grp  = lane >> 2;
    const int tig  = lane & 3;
    const int bm   = blockIdx.x * 128;
    const int wm   = warp * 16;
    const int prow = tid >> 1, pc2 = (tid & 1) * 2;
    const int vrow = tid >> 2, vc  = tid & 3;

    uint32_t psb[2] = { smem_u32(Ps[0]), smem_u32(Ps[1]) };
    uint32_t vsb[2] = { smem_u32(Vs[0]), smem_u32(Vs[1]) };

    const __half* Pg = P  + (size_t)(bm + prow) * Sn;
    const __half* Vg = Vt + (size_t)vrow * Sn;

    float acc[8][4] = {};

    cp16(psb[0] + sw_off(prow, pc2),     Pg + pc2 * 8);
    cp16(psb[0] + sw_off(prow, pc2 + 1), Pg + pc2 * 8 + 8);
    cp16(vsb[0] + sw_off(vrow, vc),      Vg + vc * 8);
    cp_commit();

    const int nIter = Sn >> 5;
    for (int it = 0; it < nIter; ++it) {
        const int buf = it & 1;
        cp_wait0();
        __syncthreads();
        if (it + 1 < nIter) {
            const int k0 = (it + 1) << 5;
            cp16(psb[buf ^ 1] + sw_off(prow, pc2),     Pg + k0 + pc2 * 8);
            cp16(psb[buf ^ 1] + sw_off(prow, pc2 + 1), Pg + k0 + pc2 * 8 + 8);
            cp16(vsb[buf ^ 1] + sw_off(vrow, vc),      Vg + k0 + vc * 8);
            cp_commit();
        }
        #pragma unroll
        for (int ks = 0; ks < 2; ++ks) {
            const int frow = (lane & 7) + ((lane >> 3) & 1) * 8;
            const int fch  = ks * 2 + (lane >> 4);
            uint32_t a[4];
            ldsm4(a[0], a[1], a[2], a[3], psb[buf] + sw_off(wm + frow, fch));
            uint32_t bfr[8][2];
            #pragma unroll
            for (int nj = 0; nj < 4; ++nj) {
                uint32_t r0, r1, r2, r3;
                ldsm4(r0, r1, r2, r3, vsb[buf] + sw_off(nj * 16 + frow, fch));
                bfr[nj * 2][0] = r0;  bfr[nj * 2][1] = r2;
                bfr[nj * 2 + 1][0] = r1;  bfr[nj * 2 + 1][1] = r3;
            }
            #pragma unroll
            for (int ni = 0; ni < 8; ++ni)
                mma16816(acc[ni], a[0], a[1], a[2], a[3], bfr[ni][0], bfr[ni][1]);
        }
    }

    const int r0 = bm + wm + grp;
    #pragma unroll
    for (int ni = 0; ni < 8; ++ni) {
        const int c0 = ni * 8 + 2 * tig;
        *(__half2*)&C[(size_t)r0 * Dn + c0]       = __floats2half2_rn(acc[ni][0], acc[ni][1]);
        *(__half2*)&C[(size_t)(r0 + 8) * Dn + c0] = __floats2half2_rn(acc[ni][2], acc[ni][3]);
    }
}

// ---------------------------------------------------------------------------
// One-shot fp32 -> fp16 conversion of x + 4 weight matrices.
// threads [0, 512K) -> x (4M elems); then 4 x 128K threads per W (1M elems).
// ---------------------------------------------------------------------------
__global__ void __launch_bounds__(256) conv_all(
    const float* __restrict__ x,
    const float* __restrict__ Wq, const float* __restrict__ Wk,
    const float* __restrict__ Wv, const float* __restrict__ Wo)
{
    const size_t t = (size_t)blockIdx.x * 256 + threadIdx.x;
    const float* s;
    __half* d;
    size_t off;
    if (t < 524288)      { s = x;  d = g_xh;    off = t; }
    else if (t < 655360) { s = Wq; d = g_Wh[0]; off = t - 524288; }
    else if (t < 786432) { s = Wk; d = g_Wh[1]; off = t - 655360; }
    else if (t < 917504) { s = Wv; d = g_Wh[2]; off = t - 786432; }
    else                 { s = Wo; d = g_Wh[3]; off = t - 917504; }
    const size_t i = off * 8;
    float4 a = *(const float4*)(s + i);
    float4 b = *(const float4*)(s + i + 4);
    __half2 h0 = __floats2half2_rn(a.x, a.y), h1 = __floats2half2_rn(a.z, a.w);
    __half2 h2 = __floats2half2_rn(b.x, b.y), h3 = __floats2half2_rn(b.z, b.w);
    uint4 o;
    o.x = *(uint32_t*)&h0; o.y = *(uint32_t*)&h1;
    o.z = *(uint32_t*)&h2; o.w = *(uint32_t*)&h3;
    *(uint4*)(d + i) = o;
}

// ---------------------------------------------------------------------------
extern "C" void kernel_launch(void* const* d_in, const int* in_sizes, int n_in,
                              void* d_out, int out_size)
{
    const float* x  = (const float*)d_in[0];
    const float* Wq = (const float*)d_in[1];
    const float* bq = (const float*)d_in[2];
    const float* Wk = (const float*)d_in[3];
    const float* bk = (const float*)d_in[4];
    const float* Wv = (const float*)d_in[5];
    const float* bv = (const float*)d_in[6];
    const float* Wo = (const float*)d_in[7];
    const float* bo = (const float*)d_in[8];
    float* out = (float*)d_out;

    __half *xh, *Wh, *AOh;
    cudaGetSymbolAddress((void**)&xh,  g_xh);
    cudaGetSymbolAddress((void**)&Wh,  g_Wh);
    cudaGetSymbolAddress((void**)&AOh, g_AOh);

    const size_t WN = (size_t)Dn * Dn;

    // launch 0: all conversions
    conv_all<<<4096, 256>>>(x, Wq, Wk, Wv, Wo);

    // launch 1: fused QKV projections
    dim3 gqkv(Dn / 128, Mn / 128, 3);
    qkv_h<<<gqkv, 256>>>(xh, bq, bk, bv);

    // launch 2: V transpose
    dim3 gtr(Sn / 64, Dn / 64, Bn);
    transpose_v<<<gtr, 256>>>();

    // launch 3: scores (fp16 out)
    dim3 gs(Sn / 128, Sn / 128, Bn * Hn);
    scores_h<<<gs, 256>>>();

    // launch 4: softmax over head axis, in place (2 positions/thread)
    const size_t tot2 = (size_t)Bn * Sn * Sn / 2;
    softmax_h16<<<(unsigned)(tot2 / 256), 256>>>();

    // launch 5: attn @ V   (<- profiled by ncu -s 5 -c 1)
    dim3 gav(Sn / 128, 1, Bn * Hn);
    av_h<<<gav, 256>>>();

    // launch 6: output projection
    dim3 gproj(Dn / 128, Mn / 128);
    proj_f<<<gproj, 256>>>(AOh, Wh + 3 * WN, bo, out);
}